// round 4
// baseline (speedup 1.0000x reference)
#include <cuda_runtime.h>

#define T_SEQ 256
#define NH 8
#define DHD 64
#define DMODEL 512
#define NPROJ 2560   // 5 * 512

// ---------------- scratch ----------------
__device__ float g_proj[T_SEQ * NPROJ];            // [t, 2560]
__device__ float g_M[NH * T_SEQ * DHD * DHD];      // [n, q, k, j]
__device__ float g_G[NH * T_SEQ * DHD * DHD];      // [n, q, a, c]
__device__ float g_l[NH * T_SEQ];                  // softmax denominators
__device__ float g_z[T_SEQ * DMODEL];              // [q, n*64+e] (unnormalized accum)

// ---------------- K0: zero z ----------------
__global__ __launch_bounds__(256) void zero_z_kernel() {
    g_z[blockIdx.x * 256 + threadIdx.x] = 0.f;
}

// ---------------- K1: C[M,N] = A[M,K] @ B[K,N] + bias ----------------
__global__ __launch_bounds__(256) void gemm_nn_bias_kernel(
    const float* __restrict__ A, const float* __restrict__ B,
    const float* __restrict__ bias, float* __restrict__ C,
    int M, int N, int K) {
    __shared__ float AsT[32 * 68];   // k-major: [k][m]
    __shared__ float Bs[32 * 68];    // [k][n]
    const int tid = threadIdx.x;
    const int bm = blockIdx.y * 64;
    const int bn = blockIdx.x * 64;
    const int r0 = (tid & 15) * 4;
    const int c0 = (tid >> 4) * 4;
    const int arow = tid >> 3;          // 0..31
    const int acol = (tid & 7) * 4;     // 0..28 (k)
    const int brow = tid >> 4;          // 0..15
    const int bcol = (tid & 15) * 4;    // 0..60
    float acc[4][4] = {};
    for (int k0 = 0; k0 < K; k0 += 32) {
#pragma unroll
        for (int rr = 0; rr < 2; rr++) {
            int r = arow + rr * 32;
            float4 v = *reinterpret_cast<const float4*>(&A[(size_t)(bm + r) * K + k0 + acol]);
            AsT[(acol + 0) * 68 + r] = v.x; AsT[(acol + 1) * 68 + r] = v.y;
            AsT[(acol + 2) * 68 + r] = v.z; AsT[(acol + 3) * 68 + r] = v.w;
        }
#pragma unroll
        for (int rr = 0; rr < 2; rr++) {
            float4 v = *reinterpret_cast<const float4*>(&B[(size_t)(k0 + brow + rr * 16) * N + bn + bcol]);
            *reinterpret_cast<float4*>(&Bs[(brow + rr * 16) * 68 + bcol]) = v;
        }
        __syncthreads();
#pragma unroll
        for (int kk = 0; kk < 32; kk++) {
            float4 a = *reinterpret_cast<const float4*>(&AsT[kk * 68 + r0]);
            float4 b = *reinterpret_cast<const float4*>(&Bs[kk * 68 + c0]);
            float av[4] = {a.x, a.y, a.z, a.w};
            float bv[4] = {b.x, b.y, b.z, b.w};
#pragma unroll
            for (int i = 0; i < 4; i++)
#pragma unroll
                for (int j = 0; j < 4; j++) acc[i][j] += av[i] * bv[j];
        }
        __syncthreads();
    }
    float4 bb = *reinterpret_cast<const float4*>(&bias[bn + c0]);
#pragma unroll
    for (int i = 0; i < 4; i++) {
        float4 o = make_float4(acc[i][0] + bb.x, acc[i][1] + bb.y, acc[i][2] + bb.z, acc[i][3] + bb.w);
        *reinterpret_cast<float4*>(&C[(size_t)(bm + r0 + i) * N + bn + c0]) = o;
    }
}

// ---------------- K2: M[n,q,kj] = sum_i qproj[q,i] * Wkq[n,kj,i] ----------------
__global__ __launch_bounds__(256) void compute_M_kernel(const float* __restrict__ Wkq) {
    __shared__ float AsT[64 * 68];   // [i][q]
    __shared__ float BsT[64 * 68];   // [i][kj]
    const int n = blockIdx.z;
    const int bq = blockIdx.y * 64;
    const int bkj = blockIdx.x * 64;
    const int tid = threadIdx.x;
    const int row = tid >> 4;           // 0..15
    const int col = (tid & 15) * 4;     // i
#pragma unroll
    for (int rr = 0; rr < 4; rr++) {
        int r = row + rr * 16;
        float4 va = *reinterpret_cast<const float4*>(&g_proj[(size_t)(bq + r) * NPROJ + 1024 + n * 64 + col]);
        AsT[(col + 0) * 68 + r] = va.x; AsT[(col + 1) * 68 + r] = va.y;
        AsT[(col + 2) * 68 + r] = va.z; AsT[(col + 3) * 68 + r] = va.w;
        float4 vb = *reinterpret_cast<const float4*>(&Wkq[(size_t)n * 262144 + (size_t)(bkj + r) * 64 + col]);
        BsT[(col + 0) * 68 + r] = vb.x; BsT[(col + 1) * 68 + r] = vb.y;
        BsT[(col + 2) * 68 + r] = vb.z; BsT[(col + 3) * 68 + r] = vb.w;
    }
    __syncthreads();
    const int q0 = (tid & 15) * 4;
    const int kj0 = (tid >> 4) * 4;
    float acc[4][4] = {};
#pragma unroll 8
    for (int i = 0; i < 64; i++) {
        float4 a = *reinterpret_cast<const float4*>(&AsT[i * 68 + q0]);
        float4 b = *reinterpret_cast<const float4*>(&BsT[i * 68 + kj0]);
        float av[4] = {a.x, a.y, a.z, a.w};
        float bv[4] = {b.x, b.y, b.z, b.w};
#pragma unroll
        for (int ii = 0; ii < 4; ii++)
#pragma unroll
            for (int jj = 0; jj < 4; jj++) acc[ii][jj] += av[ii] * bv[jj];
    }
#pragma unroll
    for (int ii = 0; ii < 4; ii++) {
        float4 o = make_float4(acc[ii][0], acc[ii][1], acc[ii][2], acc[ii][3]);
        *reinterpret_cast<float4*>(&g_M[(size_t)(n * T_SEQ + bq + q0 + ii) * 4096 + bkj + kj0]) = o;
    }
}

// ---------------- K3: main attention (512 threads, 1 CTA per (n,q)) ----------------
#define OFF_K1T 0           // [64][257] k1T (k,p) phase1; v1s [256][64] phase3
#define OFF_BT  16448       // [64][256] B transposed (j, p)
#define OFF_ET  32832       // [64][256] E transposed (t, p); RT (c,p) phase3
#define OFF_C   49216       // [64][64] M (k,j) phase1; k2T [j][t] stride 68 phase2
#define OFF_V2  53568       // [64][64] v2 (t,c) phase2; G-partial [64][64] phase3
#define OFF_RED 57664       // [16]
#define ATTN_SMEM_FLOATS 57680
#define ATTN_SMEM_BYTES (ATTN_SMEM_FLOATS * 4)

// NT = number of 64-wide t/p tiles = ceil(P/64). Per-thread p blocks = NT.
template <int NT>
__device__ __forceinline__ void attn_body(float* sm, int n, int q, int tid) {
    float* k1T = sm + OFF_K1T;   // stride 257
    float* BT  = sm + OFF_BT;    // stride 256
    float* ET  = sm + OFF_ET;    // stride 256
    float* Cr  = sm + OFF_C;     // M: stride 64 / k2T: stride 68
    float* v2s = sm + OFF_V2;    // stride 64
    float* red = sm + OFF_RED;

    const int P = q + 1;
    const int pl = tid & 31;
    const int wid = tid >> 5;         // 0..15
    const int c8 = (wid & 7) * 8;     // c/t/j slot
    const int ph = wid >> 3;          // p-half

    // ---- load M ----
    {
        const float* Mg = g_M + (size_t)(n * T_SEQ + q) * 4096;
#pragma unroll
        for (int r = 0; r < 2; r++) {
            int off = (tid + r * 512) * 4;
            *reinterpret_cast<float4*>(&Cr[off]) = *reinterpret_cast<const float4*>(&Mg[off]);
        }
    }
    // ---- load k1 transposed [k][p], zero-filled past P ----
    {
        const int rr = tid >> 4;            // 0..31
        const int iv = (tid & 15) * 4;
#pragma unroll
        for (int pass = 0; pass < NT * 2; pass++) {
            int p = pass * 32 + rr;
            float4 v = make_float4(0.f, 0.f, 0.f, 0.f);
            if (p < P) v = *reinterpret_cast<const float4*>(&g_proj[(size_t)p * NPROJ + n * 64 + iv]);
            k1T[(iv + 0) * 257 + p] = v.x;
            k1T[(iv + 1) * 257 + p] = v.y;
            k1T[(iv + 2) * 257 + p] = v.z;
            k1T[(iv + 3) * 257 + p] = v.w;
        }
    }
    __syncthreads();

    // ---- phase 1: B[p,j] = sum_k k1[p,k] * M[k,j]; store BT[j][p] ----
    {
        float acc[NT][8];
#pragma unroll
        for (int i = 0; i < NT; i++)
#pragma unroll
            for (int j = 0; j < 8; j++) acc[i][j] = 0.f;
#pragma unroll 4
        for (int k = 0; k < 64; k++) {
            float a[NT];
#pragma unroll
            for (int i = 0; i < NT; i++) a[i] = k1T[k * 257 + pl + 32 * (ph + 2 * i)];
            float4 b0 = *reinterpret_cast<const float4*>(&Cr[k * 64 + c8]);
            float4 b1 = *reinterpret_cast<const float4*>(&Cr[k * 64 + c8 + 4]);
            float b[8] = {b0.x, b0.y, b0.z, b0.w, b1.x, b1.y, b1.z, b1.w};
#pragma unroll
            for (int i = 0; i < NT; i++)
#pragma unroll
                for (int j = 0; j < 8; j++) acc[i][j] += a[i] * b[j];
        }
#pragma unroll
        for (int j = 0; j < 8; j++)
#pragma unroll
            for (int i = 0; i < NT; i++)
                BT[(c8 + j) * 256 + pl + 32 * (ph + 2 * i)] = acc[i][j];
    }
    __syncthreads();

    // ---- phase 2: stream t-tiles ----
    float R[NT][8];
#pragma unroll
    for (int i = 0; i < NT; i++)
#pragma unroll
        for (int j = 0; j < 8; j++) R[i][j] = 0.f;
    float lsum = 0.f;
#pragma unroll 1
    for (int tt = 0; tt < NT; tt++) {
        const int t0 = tt * 64;
        {   // load k2 transposed [j][t] into Cr (stride 68) + v2 [t][c], zero past P
            const int rr = tid >> 4;          // 0..31
            const int iv = (tid & 15) * 4;
#pragma unroll
            for (int pass = 0; pass < 2; pass++) {
                int t = pass * 32 + rr;
                int gt = t0 + t;
                float4 a = make_float4(0.f, 0.f, 0.f, 0.f);
                float4 b = make_float4(0.f, 0.f, 0.f, 0.f);
                if (gt < P) {
                    a = *reinterpret_cast<const float4*>(&g_proj[(size_t)gt * NPROJ + 512 + n * 64 + iv]);
                    b = *reinterpret_cast<const float4*>(&g_proj[(size_t)gt * NPROJ + 2048 + n * 64 + iv]);
                }
                Cr[(iv + 0) * 68 + t] = a.x;
                Cr[(iv + 1) * 68 + t] = a.y;
                Cr[(iv + 2) * 68 + t] = a.z;
                Cr[(iv + 3) * 68 + t] = a.w;
                *reinterpret_cast<float4*>(&v2s[t * 64 + iv]) = b;
            }
        }
        __syncthreads();
        // S[p, t=c8+jj] = sum_j B[p,j] * k2[t,j]
        float s[NT][8];
#pragma unroll
        for (int i = 0; i < NT; i++)
#pragma unroll
            for (int j = 0; j < 8; j++) s[i][j] = 0.f;
#pragma unroll 4
        for (int j = 0; j < 64; j++) {
            float a[NT];
#pragma unroll
            for (int i = 0; i < NT; i++) a[i] = BT[j * 256 + pl + 32 * (ph + 2 * i)];
            float4 b0 = *reinterpret_cast<const float4*>(&Cr[j * 68 + c8]);
            float4 b1 = *reinterpret_cast<const float4*>(&Cr[j * 68 + c8 + 4]);
            float b[8] = {b0.x, b0.y, b0.z, b0.w, b1.x, b1.y, b1.z, b1.w};
#pragma unroll
            for (int i = 0; i < NT; i++)
#pragma unroll
                for (int jj = 0; jj < 8; jj++) s[i][jj] += a[i] * b[jj];
        }
        // exp + mask + store ET[t][p]
#pragma unroll
        for (int i = 0; i < NT; i++) {
            int p = pl + 32 * (ph + 2 * i);
#pragma unroll
            for (int jj = 0; jj < 8; jj++) {
                int t = t0 + c8 + jj;
                float e = (p < P && t < P) ? __expf(s[i][jj] * 0.015625f) : 0.f;
                lsum += e;
                ET[(c8 + jj) * 256 + p] = e;
            }
        }
        __syncthreads();
        // R[p,c] += sum_t E[p,t] * v2[t,c]
#pragma unroll 4
        for (int t = 0; t < 64; t++) {
            float a[NT];
#pragma unroll
            for (int i = 0; i < NT; i++) a[i] = ET[t * 256 + pl + 32 * (ph + 2 * i)];
            float4 b0 = *reinterpret_cast<const float4*>(&v2s[t * 64 + c8]);
            float4 b1 = *reinterpret_cast<const float4*>(&v2s[t * 64 + c8 + 4]);
            float b[8] = {b0.x, b0.y, b0.z, b0.w, b1.x, b1.y, b1.z, b1.w};
#pragma unroll
            for (int i = 0; i < NT; i++)
#pragma unroll
                for (int j = 0; j < 8; j++) R[i][j] += a[i] * b[j];
        }
        __syncthreads();
    }

    // ---- stage RT[c][p] (into ET) + load v1 (into k1T region) + lsum partials ----
#pragma unroll
    for (int j = 0; j < 8; j++)
#pragma unroll
        for (int i = 0; i < NT; i++)
            ET[(c8 + j) * 256 + pl + 32 * (ph + 2 * i)] = R[i][j];
    {
        float* v1s = k1T;   // [256][64]
        const int rr = tid >> 4;
        const int iv = (tid & 15) * 4;
#pragma unroll
        for (int pass = 0; pass < NT * 2; pass++) {
            int p = pass * 32 + rr;
            if (p < P) {
                float4 v = *reinterpret_cast<const float4*>(&g_proj[(size_t)p * NPROJ + 1536 + n * 64 + iv]);
                *reinterpret_cast<float4*>(&v1s[p * 64 + iv]) = v;
            }
        }
    }
    // warp-level lsum reduce
#pragma unroll
    for (int off = 16; off > 0; off >>= 1)
        lsum += __shfl_xor_sync(0xffffffffu, lsum, off);
    if (pl == 0) red[wid] = lsum;
    __syncthreads();
    if (tid == 0) {
        float total = 0.f;
#pragma unroll
        for (int w = 0; w < 16; w++) total += red[w];
        g_l[n * T_SEQ + q] = total;
    }

    // ---- phase 3: G[a,c] = sum_{p<P} v1[p,a] * R[p,c], split over two thread halves ----
    {
        const float* v1s = k1T;
        const float* RT = ET;
        const int lt = tid & 255;
        const int a0 = (lt & 15) * 4;
        const int c0 = (lt >> 4) * 4;
        const int Ph = P >> 1;
        const int pbeg = (tid < 256) ? 0 : Ph;
        const int pend = (tid < 256) ? Ph : P;
        float acc[4][4] = {};
#pragma unroll 4
        for (int p = pbeg; p < pend; p++) {
            float4 av = *reinterpret_cast<const float4*>(&v1s[p * 64 + a0]);
            float avv[4] = {av.x, av.y, av.z, av.w};
            float rv[4];
#pragma unroll
            for (int k = 0; k < 4; k++) rv[k] = RT[(c0 + k) * 256 + p];
#pragma unroll
            for (int ka = 0; ka < 4; ka++)
#pragma unroll
                for (int kc = 0; kc < 4; kc++) acc[ka][kc] += avv[ka] * rv[kc];
        }
        if (tid >= 256) {
#pragma unroll
            for (int ka = 0; ka < 4; ka++)
#pragma unroll
                for (int kc = 0; kc < 4; kc++)
                    v2s[(a0 + ka) * 64 + c0 + kc] = acc[ka][kc];
        }
        __syncthreads();
        if (tid < 256) {
            float* Gout = g_G + (size_t)(n * T_SEQ + q) * 4096;
#pragma unroll
            for (int ka = 0; ka < 4; ka++) {
                float4 o;
                o.x = acc[ka][0] + v2s[(a0 + ka) * 64 + c0 + 0];
                o.y = acc[ka][1] + v2s[(a0 + ka) * 64 + c0 + 1];
                o.z = acc[ka][2] + v2s[(a0 + ka) * 64 + c0 + 2];
                o.w = acc[ka][3] + v2s[(a0 + ka) * 64 + c0 + 3];
                *reinterpret_cast<float4*>(&Gout[(a0 + ka) * 64 + c0]) = o;
            }
        }
    }
}

__global__ __launch_bounds__(512, 1) void attn_kernel() {
    extern __shared__ float sm[];
    const int bid = blockIdx.x;
    const int n = bid & 7;
    const int q = 255 - (bid >> 3);   // big-q CTAs first
    const int ntt = (q >> 6) + 1;     // ceil((q+1)/64)
    switch (ntt) {
        case 1: attn_body<1>(sm, n, q, threadIdx.x); break;
        case 2: attn_body<2>(sm, n, q, threadIdx.x); break;
        case 3: attn_body<3>(sm, n, q, threadIdx.x); break;
        default: attn_body<4>(sm, n, q, threadIdx.x); break;
    }
}

// ---------------- K4: z_raw += G @ W_Vq (K-split, atomics) ----------------
__global__ __launch_bounds__(256) void out_v_kernel(const float* __restrict__ Wvq) {
    __shared__ float AsT[32 * 68];  // [k][q]
    __shared__ float Bs[32 * 68];   // [k][e]
    const int n = blockIdx.y;
    const int bq = blockIdx.x * 64;
    const int ks = blockIdx.z;
    const int tid = threadIdx.x;
    const int arow = tid >> 3, acol = (tid & 7) * 4;
    const int brow = tid >> 4, bcol = (tid & 15) * 4;
    const int q0 = (tid & 15) * 4, e0 = (tid >> 4) * 4;
    float acc[4][4] = {};
    for (int k0 = ks * 1024; k0 < ks * 1024 + 1024; k0 += 32) {
#pragma unroll
        for (int rr = 0; rr < 2; rr++) {
            int r = arow + rr * 32;
            float4 v = *reinterpret_cast<const float4*>(
                &g_G[(size_t)(n * T_SEQ + bq + r) * 4096 + k0 + acol]);
            AsT[(acol + 0) * 68 + r] = v.x; AsT[(acol + 1) * 68 + r] = v.y;
            AsT[(acol + 2) * 68 + r] = v.z; AsT[(acol + 3) * 68 + r] = v.w;
        }
#pragma unroll
        for (int rr = 0; rr < 2; rr++) {
            float4 v = *reinterpret_cast<const float4*>(
                &Wvq[(size_t)n * 262144 + (size_t)(k0 + brow + rr * 16) * 64 + bcol]);
            *reinterpret_cast<float4*>(&Bs[(brow + rr * 16) * 68 + bcol]) = v;
        }
        __syncthreads();
#pragma unroll
        for (int kk = 0; kk < 32; kk++) {
            float4 a = *reinterpret_cast<const float4*>(&AsT[kk * 68 + q0]);
            float4 b = *reinterpret_cast<const float4*>(&Bs[kk * 68 + e0]);
            float av[4] = {a.x, a.y, a.z, a.w};
            float bv[4] = {b.x, b.y, b.z, b.w};
#pragma unroll
            for (int i = 0; i < 4; i++)
#pragma unroll
                for (int j = 0; j < 4; j++) acc[i][j] += av[i] * bv[j];
        }
        __syncthreads();
    }
#pragma unroll
    for (int i = 0; i < 4; i++)
#pragma unroll
        for (int j = 0; j < 4; j++)
            atomicAdd(&g_z[(size_t)(bq + q0 + i) * DMODEL + n * 64 + e0 + j], acc[i][j]);
}

// ---------------- K5: out = (z_raw * 1/l) @ W_out + b_out ----------------
__global__ __launch_bounds__(256) void gemm_out_kernel(
    const float* __restrict__ Wout, const float* __restrict__ bout, float* __restrict__ C) {
    __shared__ float AsT[32 * 68];  // [k][m]
    __shared__ float Bs[32 * 68];   // [k][n]
    const int tid = threadIdx.x;
    const int bm = blockIdx.y * 64;
    const int bn = blockIdx.x * 64;
    const int r0 = (tid & 15) * 4;
    const int c0 = (tid >> 4) * 4;
    const int arow = tid >> 3, acol = (tid & 7) * 4;
    const int brow = tid >> 4, bcol = (tid & 15) * 4;
    float acc[4][4] = {};
    for (int k0 = 0; k0 < DMODEL; k0 += 32) {
#pragma unroll
        for (int rr = 0; rr < 2; rr++) {
            int r = bm + arow + rr * 32;
            int gk = k0 + acol;
            float invl = 1.f / g_l[(gk >> 6) * T_SEQ + r];
            float4 v = *reinterpret_cast<const float4*>(&g_z[(size_t)r * DMODEL + gk]);
            AsT[(acol + 0) * 68 + arow + rr * 32] = v.x * invl;
            AsT[(acol + 1) * 68 + arow + rr * 32] = v.y * invl;
            AsT[(acol + 2) * 68 + arow + rr * 32] = v.z * invl;
            AsT[(acol + 3) * 68 + arow + rr * 32] = v.w * invl;
        }
#pragma unroll
        for (int rr = 0; rr < 2; rr++) {
            float4 v = *reinterpret_cast<const float4*>(&Wout[(size_t)(k0 + brow + rr * 16) * DMODEL + bn + bcol]);
            *reinterpret_cast<float4*>(&Bs[(brow + rr * 16) * 68 + bcol]) = v;
        }
        __syncthreads();
#pragma unroll
        for (int kk = 0; kk < 32; kk++) {
            float4 a = *reinterpret_cast<const float4*>(&AsT[kk * 68 + r0]);
            float4 b = *reinterpret_cast<const float4*>(&Bs[kk * 68 + c0]);
            float av[4] = {a.x, a.y, a.z, a.w};
            float bv[4] = {b.x, b.y, b.z, b.w};
#pragma unroll
            for (int i = 0; i < 4; i++)
#pragma unroll
                for (int j = 0; j < 4; j++) acc[i][j] += av[i] * bv[j];
        }
        __syncthreads();
    }
    float4 bb = *reinterpret_cast<const float4*>(&bout[bn + c0]);
#pragma unroll
    for (int i = 0; i < 4; i++) {
        float4 o = make_float4(acc[i][0] + bb.x, acc[i][1] + bb.y, acc[i][2] + bb.z, acc[i][3] + bb.w);
        *reinterpret_cast<float4*>(&C[(size_t)(bm + r0 + i) * DMODEL + bn + c0]) = o;
    }
}

// ---------------- launch ----------------
extern "C" void kernel_launch(void* const* d_in, const int* in_sizes, int n_in,
                              void* d_out, int out_size) {
    const float* x       = (const float*)d_in[0];
    const float* Wkkqvv  = (const float*)d_in[1];
    const float* bkkqvv  = (const float*)d_in[2];
    const float* WKq     = (const float*)d_in[3];
    const float* WVq     = (const float*)d_in[4];
    const float* Wout    = (const float*)d_in[5];
    const float* bout    = (const float*)d_in[6];
    float* out = (float*)d_out;

    float* proj_ptr = nullptr;
    cudaGetSymbolAddress((void**)&proj_ptr, g_proj);

    cudaFuncSetAttribute(attn_kernel, cudaFuncAttributeMaxDynamicSharedMemorySize, ATTN_SMEM_BYTES);

    zero_z_kernel<<<T_SEQ * DMODEL / 256, 256>>>();
    gemm_nn_bias_kernel<<<dim3(NPROJ / 64, T_SEQ / 64), 256>>>(x, Wkkqvv, bkkqvv, proj_ptr,
                                                               T_SEQ, NPROJ, DMODEL);
    compute_M_kernel<<<dim3(64, 4, NH), 256>>>(WKq);
    attn_kernel<<<NH * T_SEQ, 512, ATTN_SMEM_BYTES>>>();
    out_v_kernel<<<dim3(4, NH, 4), 256>>>(WVq);
    gemm_out_kernel<<<dim3(DMODEL / 64, T_SEQ / 64), 256>>>(Wout, bout, out);
}